// round 15
// baseline (speedup 1.0000x reference)
#include <cuda_runtime.h>
#include <cuda_bf16.h>
#include <math.h>
#include <stdint.h>

#define Bdim 2
#define Tdim 2048
#define Cdim 1024
#define Hdim 16
#define Sdim 16
#define HDdim 64
#define Mrows (Bdim*Tdim)   /* 4096 */
#define NCH 32              /* scan chunks */
#define CHT (Tdim/NCH)      /* 64 t per chunk */
#define WSZ (Cdim*Cdim)

// ---------------- device scratch (static, no allocation) ----------------
__device__ float g_xbase[Mrows*Cdim];
__device__ float g_delta[Mrows*Cdim];
__device__ float g_Bmat [Mrows*Sdim];
__device__ float g_Cmat [Mrows*Sdim];
__device__ float g_y    [Mrows*Cdim];
__device__ float g_cumD [Mrows*Cdim];
__device__ float g_hend [Bdim*NCH*Cdim*Sdim];
__device__ float g_hin  [Bdim*NCH*Cdim*Sdim];
__device__ __nv_bfloat16 g_ahi[Mrows*Cdim];
__device__ __nv_bfloat16 g_alo[Mrows*Cdim];
__device__ __nv_bfloat16 g_whi[6*WSZ];
__device__ __nv_bfloat16 g_wlo[6*WSZ];
__device__ __nv_bfloat16 g_qhi[Mrows*Cdim];
__device__ __nv_bfloat16 g_qlo[Mrows*Cdim];
__device__ __nv_bfloat16 g_khi[Mrows*Cdim];
__device__ __nv_bfloat16 g_klo[Mrows*Cdim];
__device__ __nv_bfloat16 g_vhi[Mrows*Cdim];
__device__ __nv_bfloat16 g_vlo[Mrows*Cdim];

// ---------------- mma / ldmatrix / cp.async helpers ----------------
__device__ __forceinline__ void mma_bf16(float* d, const uint32_t* a, const uint32_t* b) {
    asm volatile(
        "mma.sync.aligned.m16n8k16.row.col.f32.bf16.bf16.f32 "
        "{%0,%1,%2,%3}, {%4,%5,%6,%7}, {%8,%9}, {%0,%1,%2,%3};"
        : "+f"(d[0]), "+f"(d[1]), "+f"(d[2]), "+f"(d[3])
        : "r"(a[0]), "r"(a[1]), "r"(a[2]), "r"(a[3]), "r"(b[0]), "r"(b[1]));
}
#define LDSM4(r0, r1, r2, r3, addr) \
    asm volatile("ldmatrix.sync.aligned.m8n8.x4.shared.b16 {%0,%1,%2,%3}, [%4];" \
        : "=r"(r0), "=r"(r1), "=r"(r2), "=r"(r3) : "r"(addr))
#define LDSM4T(r0, r1, r2, r3, addr) \
    asm volatile("ldmatrix.sync.aligned.m8n8.x4.trans.shared.b16 {%0,%1,%2,%3}, [%4];" \
        : "=r"(r0), "=r"(r1), "=r"(r2), "=r"(r3) : "r"(addr))
#define CP_ASYNC16(dst, src) \
    asm volatile("cp.async.cg.shared.global [%0], [%1], 16;" :: "r"(dst), "l"(src))
#define CP_COMMIT() asm volatile("cp.async.commit_group;" ::: "memory")
#define CP_WAIT0()  asm volatile("cp.async.wait_group 0;" ::: "memory")

__device__ __forceinline__ uint32_t smem_u32(const void* p) {
    uint32_t a;
    asm("{ .reg .u64 t; cvta.to.shared.u64 t, %1; cvt.u32.u64 %0, t; }"
        : "=r"(a) : "l"(p));
    return a;
}
__device__ __forceinline__ void split_pack(float x, float y, uint32_t& hi, uint32_t& lo) {
    __nv_bfloat16 hx = __float2bfloat16_rn(x), hy = __float2bfloat16_rn(y);
    hi = (uint32_t)__bfloat16_as_ushort(hx) | ((uint32_t)__bfloat16_as_ushort(hy) << 16);
    __nv_bfloat16 lx = __float2bfloat16_rn(x - __bfloat162float(hx));
    __nv_bfloat16 ly = __float2bfloat16_rn(y - __bfloat162float(hy));
    lo = (uint32_t)__bfloat16_as_ushort(lx) | ((uint32_t)__bfloat16_as_ushort(ly) << 16);
}

// ---------------- conversion kernels ----------------
__global__ __launch_bounds__(256)
void actconv_kernel(const float* __restrict__ src,
                    __nv_bfloat16* __restrict__ hi, __nv_bfloat16* __restrict__ lo)
{
    size_t i = ((size_t)blockIdx.x * 256 + threadIdx.x) * 4;
    float4 v = *(const float4*)(src + i);
    __nv_bfloat16 h0 = __float2bfloat16_rn(v.x);
    __nv_bfloat16 h1 = __float2bfloat16_rn(v.y);
    __nv_bfloat16 h2 = __float2bfloat16_rn(v.z);
    __nv_bfloat16 h3 = __float2bfloat16_rn(v.w);
    __nv_bfloat16 l0 = __float2bfloat16_rn(v.x - __bfloat162float(h0));
    __nv_bfloat16 l1 = __float2bfloat16_rn(v.y - __bfloat162float(h1));
    __nv_bfloat16 l2 = __float2bfloat16_rn(v.z - __bfloat162float(h2));
    __nv_bfloat16 l3 = __float2bfloat16_rn(v.w - __bfloat162float(h3));
    ushort4 uh, ul;
    uh.x = __bfloat16_as_ushort(h0); uh.y = __bfloat16_as_ushort(h1);
    uh.z = __bfloat16_as_ushort(h2); uh.w = __bfloat16_as_ushort(h3);
    ul.x = __bfloat16_as_ushort(l0); ul.y = __bfloat16_as_ushort(l1);
    ul.z = __bfloat16_as_ushort(l2); ul.w = __bfloat16_as_ushort(l3);
    *(ushort4*)(hi + i) = uh;
    *(ushort4*)(lo + i) = ul;
}

// All 6 weights in ONE launch
__global__ __launch_bounds__(256)
void wconv_all_kernel(const float* __restrict__ W0, const float* __restrict__ W1,
                      const float* __restrict__ W2, const float* __restrict__ W3,
                      const float* __restrict__ W4, const float* __restrict__ W5,
                      __nv_bfloat16* __restrict__ whi, __nv_bfloat16* __restrict__ wlo)
{
    __shared__ float ts[32][33];
    const int wsel = blockIdx.z;
    const float* W;
    switch (wsel) {
        case 0: W = W0; break;
        case 1: W = W1; break;
        case 2: W = W2; break;
        case 3: W = W3; break;
        case 4: W = W4; break;
        default: W = W5; break;
    }
    __nv_bfloat16* oh = whi + (size_t)wsel * WSZ;
    __nv_bfloat16* ol = wlo + (size_t)wsel * WSZ;

    const int tid = threadIdx.x;
    const int tx = tid & 31, ty = tid >> 5;
    const int n0 = blockIdx.x * 32, k0 = blockIdx.y * 32;
#pragma unroll
    for (int i = 0; i < 4; i++)
        ts[ty + 8 * i][tx] = W[(size_t)(k0 + ty + 8 * i) * Cdim + n0 + tx];
    __syncthreads();
#pragma unroll
    for (int i = 0; i < 4; i++) {
        int r = ty + 8 * i;
        float x = ts[tx][r];
        __nv_bfloat16 h = __float2bfloat16_rn(x);
        __nv_bfloat16 l = __float2bfloat16_rn(x - __bfloat162float(h));
        size_t o = (size_t)(n0 + r) * Cdim + k0 + tx;
        oh[o] = h;
        ol[o] = l;
    }
}

// ---------------- bf16 split tensor GEMM (ldmatrix + cp.async pipeline) --
#define SPITCH 40
#define STG_ELEM (4 * 128 * SPITCH)
#define STG_BYTES (STG_ELEM * 2)
#define ARR_BYTES (128 * SPITCH * 2)
#define BG_SMEM (2 * STG_BYTES)
template<int MODE>
__global__ __launch_bounds__(256, 2)
void bgemm_kernel(const __nv_bfloat16* __restrict__ Ahi, const __nv_bfloat16* __restrict__ Alo,
                  const __nv_bfloat16* __restrict__ Whi, const __nv_bfloat16* __restrict__ Wlo,
                  const float* __restrict__ bias, float* __restrict__ out,
                  __nv_bfloat16* __restrict__ outH, __nv_bfloat16* __restrict__ outL)
{
    extern __shared__ __nv_bfloat16 smb[];

    const int tid  = threadIdx.x;
    const int lane = tid & 31;
    const int warp = tid >> 5;
    const int wm   = (warp >> 2) * 64;
    const int wn   = (warp & 3) * 32;
    const int gr   = lane >> 2;
    const int ctid = lane & 3;
    const int c2   = ctid * 2;
    const int row0 = blockIdx.y * 128;
    const int col0 = blockIdx.x * 128;

    float acc[4][4][4];
#pragma unroll
    for (int i = 0; i < 4; i++)
#pragma unroll
        for (int j = 0; j < 4; j++)
#pragma unroll
            for (int e = 0; e < 4; e++) acc[i][j][e] = 0.f;

    const uint32_t smB = smem_u32(smb);
    uint32_t aad[4], bad[2];
    {
        int arl = lane & 15;
        int ako = (lane >> 4) << 3;
#pragma unroll
        for (int mt = 0; mt < 4; mt++)
            aad[mt] = smB + ((wm + mt * 16 + arl) * SPITCH + ako) * 2;
        int bro = ((lane >> 4) << 3) + (lane & 7);
        int bko = ((lane >> 3) & 1) << 3;
#pragma unroll
        for (int P = 0; P < 2; P++)
            bad[P] = smB + 2 * ARR_BYTES + ((wn + P * 16 + bro) * SPITCH + bko) * 2;
    }

    const int lrow = tid >> 1;
    const int lseg = (tid & 1) * 16;
    const uint32_t sby = (uint32_t)(lrow * SPITCH + lseg) * 2;
    const size_t gAb = (size_t)(row0 + lrow) * Cdim + lseg;
    const size_t gBb = (size_t)(col0 + lrow) * Cdim + lseg;

    {
        uint32_t d0 = smB + sby;
        CP_ASYNC16(d0,                 Ahi + gAb);
        CP_ASYNC16(d0 + 16,            Ahi + gAb + 8);
        CP_ASYNC16(d0 + ARR_BYTES,     Alo + gAb);
        CP_ASYNC16(d0 + ARR_BYTES+16,  Alo + gAb + 8);
        CP_ASYNC16(d0 + 2*ARR_BYTES,   Whi + gBb);
        CP_ASYNC16(d0 + 2*ARR_BYTES+16,Whi + gBb + 8);
        CP_ASYNC16(d0 + 3*ARR_BYTES,   Wlo + gBb);
        CP_ASYNC16(d0 + 3*ARR_BYTES+16,Wlo + gBb + 8);
        CP_COMMIT();
    }

    for (int ch = 0; ch < 32; ch++) {
        CP_WAIT0();
        __syncthreads();

        if (ch + 1 < 32) {
            int k0 = (ch + 1) * 32;
            uint32_t d0 = smB + ((ch + 1) & 1) * STG_BYTES + sby;
            CP_ASYNC16(d0,                 Ahi + gAb + k0);
            CP_ASYNC16(d0 + 16,            Ahi + gAb + k0 + 8);
            CP_ASYNC16(d0 + ARR_BYTES,     Alo + gAb + k0);
            CP_ASYNC16(d0 + ARR_BYTES+16,  Alo + gAb + k0 + 8);
            CP_ASYNC16(d0 + 2*ARR_BYTES,   Whi + gBb + k0);
            CP_ASYNC16(d0 + 2*ARR_BYTES+16,Whi + gBb + k0 + 8);
            CP_ASYNC16(d0 + 3*ARR_BYTES,   Wlo + gBb + k0);
            CP_ASYNC16(d0 + 3*ARR_BYTES+16,Wlo + gBb + k0 + 8);
            CP_COMMIT();
        }

        const uint32_t sb = (ch & 1) * STG_BYTES;
#pragma unroll
        for (int ks = 0; ks < 2; ks++) {
            const uint32_t ksb = sb + ks * 32;
            uint32_t ahf[4][4], alf[4][4];
#pragma unroll
            for (int mt = 0; mt < 4; mt++) {
                LDSM4(ahf[mt][0], ahf[mt][1], ahf[mt][2], ahf[mt][3], aad[mt] + ksb);
                LDSM4(alf[mt][0], alf[mt][1], alf[mt][2], alf[mt][3], aad[mt] + ksb + ARR_BYTES);
            }
            uint32_t bhf[4][2], blf[4][2];
#pragma unroll
            for (int P = 0; P < 2; P++) {
                LDSM4(bhf[2*P][0], bhf[2*P][1], bhf[2*P+1][0], bhf[2*P+1][1], bad[P] + ksb);
                LDSM4(blf[2*P][0], blf[2*P][1], blf[2*P+1][0], blf[2*P+1][1], bad[P] + ksb + ARR_BYTES);
            }
#pragma unroll
            for (int mt = 0; mt < 4; mt++)
#pragma unroll
                for (int nt = 0; nt < 4; nt++) {
                    mma_bf16(acc[mt][nt], ahf[mt], bhf[nt]);
                    mma_bf16(acc[mt][nt], alf[mt], bhf[nt]);
                    mma_bf16(acc[mt][nt], ahf[mt], blf[nt]);
                }
        }
    }

#pragma unroll
    for (int mt = 0; mt < 4; mt++) {
#pragma unroll
        for (int nt = 0; nt < 4; nt++) {
            int c = col0 + wn + nt * 8 + c2;
            float2 bb = *(const float2*)(bias + c);
#pragma unroll
            for (int half = 0; half < 2; half++) {
                int r = row0 + wm + mt * 16 + gr + half * 8;
                float vx = acc[mt][nt][half * 2 + 0] + bb.x;
                float vy = acc[mt][nt][half * 2 + 1] + bb.y;
                if (MODE == 1) {
                    vx = (vx > 20.f) ? vx : log1pf(expf(vx));
                    vy = (vy > 20.f) ? vy : log1pf(expf(vy));
                }
                if (MODE == 2) {
                    int b = r >> 11, t = r & (Tdim - 1);
                    int hh = c >> 6, d = c & 63;
                    size_t di = (((size_t)(b * Hdim + hh) * Tdim + t) << 6) + d;
                    uint32_t ph, pl;
                    split_pack(vx, vy, ph, pl);
                    *(uint32_t*)(outH + di) = ph;
                    *(uint32_t*)(outL + di) = pl;
                } else {
                    *(float2*)(out + (size_t)r * Cdim + c) = make_float2(vx, vy);
                }
            }
        }
    }
}

// ---------------- skinny GEMM ----------------
__global__ __launch_bounds__(256)
void skinny_kernel(const float* __restrict__ x, const float* __restrict__ WB,
                   const float* __restrict__ WC,
                   float* __restrict__ Bm, float* __restrict__ Cm)
{
    __shared__ float wb[128 * 16];
    __shared__ float wc[128 * 16];
    __shared__ float xs[16][128];
    const int tid = threadIdx.x;
    const int m0  = blockIdx.x * 16;
    const int rl  = tid >> 4;
    const int s   = tid & 15;
    float accB = 0.f, accC = 0.f;

    for (int k0 = 0; k0 < Cdim; k0 += 128) {
#pragma unroll
        for (int u = 0; u < 2; u++) {
            int idx = tid * 8 + u * 4;
            *(float4*)&wb[idx] = *(const float4*)(WB + k0 * 16 + idx);
            *(float4*)&wc[idx] = *(const float4*)(WC + k0 * 16 + idx);
        }
        {
            int row = tid >> 4;
            int cc  = (tid & 15) * 8;
            const float* xp = x + (size_t)(m0 + row) * Cdim + k0 + cc;
            *(float4*)&xs[row][cc]     = *(const float4*)(xp);
            *(float4*)&xs[row][cc + 4] = *(const float4*)(xp + 4);
        }
        __syncthreads();
#pragma unroll 8
        for (int kk = 0; kk < 128; kk++) {
            float xv = xs[rl][kk];
            accB = fmaf(xv, wb[kk * 16 + s], accB);
            accC = fmaf(xv, wc[kk * 16 + s], accC);
        }
        __syncthreads();
    }
    Bm[(size_t)(m0 + rl) * 16 + s] = accB;
    Cm[(size_t)(m0 + rl) * 16 + s] = accC;
}

// ================= chunked SSM scan =================
#define TTA 32
__global__ __launch_bounds__(256)
void scanA_kernel(const float* __restrict__ A_log,
                  const float* __restrict__ delta,
                  const float* __restrict__ xb,
                  const float* __restrict__ Bm,
                  const float* __restrict__ Cm,
                  float* __restrict__ ylocal,
                  float* __restrict__ cumD,
                  float* __restrict__ hend)
{
    __shared__ float2 sdx[TTA][16];
    __shared__ float2 sbc[TTA][16];

    const int tid = threadIdx.x;
    const int s   = tid & 15;
    const int cl  = tid >> 4;
    const int c0  = blockIdx.x * 16;
    const int ch  = blockIdx.y;
    const int b   = blockIdx.z;
    const int c   = c0 + cl;
    const int t00 = ch * CHT;
    const float LOG2E = 1.4426950408889634f;
    const float a2 = -expf(A_log[c * Sdim + s]) * LOG2E;

    float h = 0.f, cum = 0.f;

    for (int t0 = t00; t0 < t00 + CHT; t0 += TTA) {
        __syncthreads();
#pragma unroll
        for (int u = 0; u < 2; u++) {
            int e = tid + u * 256;
            int tt = e >> 4, cc = e & 15;
            size_t g = ((size_t)b * Tdim + t0 + tt) * Cdim + c0 + cc;
            sdx[tt][cc] = make_float2(delta[g], xb[g]);
        }
#pragma unroll
        for (int u = 0; u < 2; u++) {
            int e = tid + u * 256;
            int tt = e >> 4, ss = e & 15;
            size_t g = ((size_t)b * Tdim + t0 + tt) * Sdim + ss;
            sbc[tt][ss] = make_float2(Bm[g], Cm[g]);
        }
        __syncthreads();

#pragma unroll
        for (int tt = 0; tt < TTA; tt++) {
            float2 dx = sdx[tt][cl];
            float2 bc = sbc[tt][s];
            cum += dx.x;
            float e = exp2f(dx.x * a2);
            h = fmaf(e, h, dx.x * dx.y * bc.x);
            float p = h * bc.y;
            p += __shfl_xor_sync(0xffffffffu, p, 8);
            p += __shfl_xor_sync(0xffffffffu, p, 4);
            p += __shfl_xor_sync(0xffffffffu, p, 2);
            p += __shfl_xor_sync(0xffffffffu, p, 1);
            if (s == 0) {
                size_t g = ((size_t)b * Tdim + t0 + tt) * Cdim + c;
                ylocal[g] = p;
                cumD[g]   = cum;
            }
        }
    }
    hend[(((size_t)b * NCH + ch) * Cdim + c) * Sdim + s] = h;
}

__global__ __launch_bounds__(256)
void scanB_kernel(const float* __restrict__ A_log,
                  const float* __restrict__ cumD,
                  const float* __restrict__ hend,
                  float* __restrict__ hin)
{
    const int gid = blockIdx.x * 256 + threadIdx.x;
    const int s = gid & 15;
    const int c = (gid >> 4) & (Cdim - 1);
    const int b = gid >> 14;
    const float LOG2E = 1.4426950408889634f;
    const float a2 = -expf(A_log[c * Sdim + s]) * LOG2E;

    float h = 0.f;
#pragma unroll
    for (int k = 0; k < NCH; k++) {
        size_t idx = (((size_t)b * NCH + k) * Cdim + c) * Sdim + s;
        hin[idx] = h;
        float sd = cumD[((size_t)b * Tdim + k * CHT + CHT - 1) * Cdim + c];
        h = fmaf(exp2f(a2 * sd), h, hend[idx]);
    }
}

__global__ __launch_bounds__(256)
void scanC_kernel(const float* __restrict__ A_log,
                  const float* __restrict__ Cm,
                  const float* __restrict__ hin,
                  const float* __restrict__ cumD,
                  float* __restrict__ y)
{
    __shared__ float a2s[16][17];
    __shared__ float hns[16][17];
    __shared__ float cts[16][16];

    const int tid = threadIdx.x;
    const int c0  = blockIdx.x * 16;
    const int t0  = blockIdx.y * 16;
    const int b   = blockIdx.z;
    const int ch  = t0 / CHT;
    const float LOG2E = 1.4426950408889634f;

    {
        int i = tid >> 4, j = tid & 15;
        a2s[i][j] = -expf(A_log[(c0 + i) * Sdim + j]) * LOG2E;
        hns[i][j] = hin[(((size_t)b * NCH + ch) * Cdim + c0 + i) * Sdim + j];
        cts[i][j] = Cm[((size_t)b * Tdim + t0 + i) * Sdim + j];
    }
    __syncthreads();

    const int tl = tid >> 4;
    const int cl = tid & 15;
    size_t g = ((size_t)b * Tdim + t0 + tl) * Cdim + c0 + cl;
    float cd  = cumD[g];
    float acc = y[g];
#pragma unroll
    for (int s = 0; s < 16; s++)
        acc = fmaf(cts[tl][s] * hns[cl][s], exp2f(a2s[cl][s] * cd), acc);
    y[g] = acc;
}

// ---------------- add + LayerNorm, emits bf16 hi/lo directly -------------
__global__ __launch_bounds__(256)
void addln_kernel(const float* __restrict__ xb, const float* __restrict__ y,
                  const float* __restrict__ gam, const float* __restrict__ bet,
                  __nv_bfloat16* __restrict__ ohi, __nv_bfloat16* __restrict__ olo)
{
    __shared__ float red[16];
    const int row = blockIdx.x, tid = threadIdx.x;
    const float* p1 = xb + (size_t)row * Cdim;
    const float* p2 = y  + (size_t)row * Cdim;
    float v[4]; float s = 0.f, s2 = 0.f;
#pragma unroll
    for (int i = 0; i < 4; i++) {
        int idx = tid + i * 256;
        v[i] = p1[idx] + p2[idx];
        s += v[i]; s2 += v[i] * v[i];
    }
#pragma unroll
    for (int o = 16; o; o >>= 1) {
        s  += __shfl_xor_sync(0xffffffffu, s,  o);
        s2 += __shfl_xor_sync(0xffffffffu, s2, o);
    }
    if ((tid & 31) == 0) { red[tid >> 5] = s; red[(tid >> 5) + 8] = s2; }
    __syncthreads();
    float S = 0.f, S2 = 0.f;
#pragma unroll
    for (int w = 0; w < 8; w++) { S += red[w]; S2 += red[w + 8]; }
    float mean = S * (1.f / Cdim);
    float var  = S2 * (1.f / Cdim) - mean * mean;
    float rs   = rsqrtf(var + 1e-5f);
#pragma unroll
    for (int i = 0; i < 4; i++) {
        int idx = tid + i * 256;
        float val = (v[i] - mean) * rs * gam[idx] + bet[idx];
        __nv_bfloat16 h = __float2bfloat16_rn(val);
        __nv_bfloat16 l = __float2bfloat16_rn(val - __bfloat162float(h));
        ohi[(size_t)row * Cdim + idx] = h;
        olo[(size_t)row * Cdim + idx] = l;
    }
}

// ---------------- flash attention on tensor cores (bf16 3-pass) ----------
// Single-exchange online softmax: each warp-half publishes (local max, local sum)
// once per tile; correction factors folded into P-pack and l update.
#define FP 72
#define FL_ARRE 4608
#define FL_ARRB 9216
#define FL_Q0 0
#define FL_Q1 FL_ARRE
#define FL_ST (2*FL_ARRE)
#define FL_STGB (4*FL_ARRB)
#define FL_F32 (FL_ST + 8*FL_ARRE)
#define FL_SMEM (FL_F32*2 + 1024)
__global__ __launch_bounds__(256, 2)
void flash_kernel(const __nv_bfloat16* __restrict__ qhi, const __nv_bfloat16* __restrict__ qlo,
                  const __nv_bfloat16* __restrict__ khi, const __nv_bfloat16* __restrict__ klo,
                  const __nv_bfloat16* __restrict__ vhi, const __nv_bfloat16* __restrict__ vlo,
                  const float* __restrict__ temp,
                  __nv_bfloat16* __restrict__ ohi, __nv_bfloat16* __restrict__ olo)
{
    extern __shared__ __nv_bfloat16 fsm[];
    const uint32_t smB = smem_u32(fsm);
    float* pmax = (float*)(fsm + FL_F32);
    float* psum = pmax + 128;

    const int tid = threadIdx.x;
    const int lane = tid & 31;
    const int warp = tid >> 5;
    const int wm   = (warp >> 1) * 16;
    const int nh   = warp & 1;
    const int gr   = lane >> 2;
    const int ctid = lane & 3;
    const int c2   = ctid * 2;

    const int qt = blockIdx.x, h = blockIdx.y, b = blockIdx.z;
    const int bh = b * Hdim + h;
    const __nv_bfloat16* qhb = qhi + (((size_t)bh * Tdim) + qt * 64) * 64;
    const __nv_bfloat16* qlb = qlo + (((size_t)bh * Tdim) + qt * 64) * 64;
    const __nv_bfloat16* khb = khi + ((size_t)bh * Tdim) * 64;
    const __nv_bfloat16* klb = klo + ((size_t)bh * Tdim) * 64;
    const __nv_bfloat16* vhb = vhi + ((size_t)bh * Tdim) * 64;
    const __nv_bfloat16* vlb = vlo + ((size_t)bh * Tdim) * 64;

    float tv = temp[h];
    float sp = (tv > 20.f) ? tv : log1pf(expf(tv));
    const float sc = sp * (1.4426950408889634f / 8.0f);

    {
        int row = tid >> 2, col = (tid & 3) * 16;
        *(uint4*)&fsm[FL_Q0 + row * FP + col]     = *(const uint4*)(qhb + row * 64 + col);
        *(uint4*)&fsm[FL_Q0 + row * FP + col + 8] = *(const uint4*)(qhb + row * 64 + col + 8);
        *(uint4*)&fsm[FL_Q1 + row * FP + col]     = *(const uint4*)(qlb + row * 64 + col);
        *(uint4*)&fsm[FL_Q1 + row * FP + col + 8] = *(const uint4*)(qlb + row * 64 + col + 8);
    }

    const int arl = lane & 15;
    const int ako = (lane >> 4) << 3;
    const uint32_t aQh = smB + (FL_Q0 + (wm + arl) * FP + ako) * 2;
    const uint32_t aQl = smB + (FL_Q1 + (wm + arl) * FP + ako) * 2;
    const int bro = ((lane >> 4) << 3) + (lane & 7);
    const int bko = ((lane >> 3) & 1) << 3;
    const uint32_t bKoff = (uint32_t)((nh * 32 + bro) * FP + bko) * 2;
    const uint32_t vOff = (uint32_t)(((((lane >> 3) & 1) * 8 + (lane & 7)) * FP) + ((lane >> 4) * 8)) * 2;

    const int ca = tid >> 6;
    const int crow = tid & 63;
    const __nv_bfloat16* csrc = (ca == 0) ? khb : (ca == 1) ? klb : (ca == 2) ? vhb : vlb;

    float m0 = -1e30f, m1 = -1e30f, l0 = 0.f, l1 = 0.f;
    float oacc[8][4];
#pragma unroll
    for (int nt = 0; nt < 8; nt++)
#pragma unroll
        for (int e = 0; e < 4; e++) oacc[nt][e] = 0.f;

    {
        uint32_t dst = smB + FL_ST * 2 + ca * FL_ARRB + crow * (FP * 2);
        const __nv_bfloat16* g = csrc + (size_t)crow * 64;
#pragma unroll
        for (int c = 0; c < 8; c++) CP_ASYNC16(dst + c * 16, g + c * 8);
        CP_COMMIT();
    }

    for (int j = 0; j <= qt; j++) {
        CP_WAIT0();
        __syncthreads();

        if (j + 1 <= qt) {
            uint32_t dst = smB + FL_ST * 2 + ((j + 1) & 1) * FL_STGB + ca * FL_ARRB + crow * (FP * 2);
            const __nv_bfloat16* g = csrc + (size_t)((j + 1) * 64 + crow) * 64;
#pragma unroll
            for (int c = 0; c < 8; c++) CP_ASYNC16(dst + c * 16, g + c * 8);
            CP_COMMIT();
        }

        const uint32_t stgB = smB + FL_ST * 2 + (j & 1) * FL_STGB;
        const uint32_t kHi = stgB + bKoff;
        const uint32_t kLo = kHi + FL_ARRB;
        const uint32_t vHi = stgB + 2 * FL_ARRB + vOff;
        const uint32_t vLo = vHi + FL_ARRB;

        float sacc[4][4];
#pragma unroll
        for (int nt = 0; nt < 4; nt++)
#pragma unroll
            for (int e = 0; e < 4; e++) sacc[nt][e] = 0.f;
#pragma unroll
        for (int kb = 0; kb < 4; kb++) {
            uint32_t ah[4], al_[4];
            LDSM4(ah[0], ah[1], ah[2], ah[3], aQh + kb * 32);
            LDSM4(al_[0], al_[1], al_[2], al_[3], aQl + kb * 32);
            uint32_t bh_[4][2], bl_[4][2];
#pragma unroll
            for (int P = 0; P < 2; P++) {
                LDSM4(bh_[2*P][0], bh_[2*P][1], bh_[2*P+1][0], bh_[2*P+1][1], kHi + P * (16 * FP * 2) + kb * 32);
                LDSM4(bl_[2*P][0], bl_[2*P][1], bl_[2*P+1][0], bl_[2*P+1][1], kLo + P * (16 * FP * 2) + kb * 32);
            }
#pragma unroll
            for (int nt = 0; nt < 4; nt++) {
                mma_bf16(sacc[nt], ah,  bh_[nt]);
                mma_bf16(sacc[nt], al_, bh_[nt]);
                mma_bf16(sacc[nt], ah,  bl_[nt]);
            }
        }

        // ---- scale, mask; LOCAL softmax stats (per warp-half) ----
        const bool diag = (j == qt);
        float sv0[8], sv1[8];
#pragma unroll
        for (int nt = 0; nt < 4; nt++)
#pragma unroll
            for (int e = 0; e < 2; e++) {
                int cl = nh * 32 + nt * 8 + c2 + e;
                float x0 = sacc[nt][e]     * sc;
                float x1 = sacc[nt][2 + e] * sc;
                if (diag) {
                    if (cl > wm + gr)     x0 = -1e30f;
                    if (cl > wm + gr + 8) x1 = -1e30f;
                }
                sv0[nt * 2 + e] = x0;
                sv1[nt * 2 + e] = x1;
            }
        float pm0 = sv0[0], pm1 = sv1[0];
#pragma unroll
        for (int i = 1; i < 8; i++) { pm0 = fmaxf(pm0, sv0[i]); pm1 = fmaxf(pm1, sv1[i]); }
        pm0 = fmaxf(pm0, __shfl_xor_sync(0xffffffffu, pm0, 1));
        pm0 = fmaxf(pm0, __shfl_xor_sync(0xffffffffu, pm0, 2));
        pm1 = fmaxf(pm1, __shfl_xor_sync(0xffffffffu, pm1, 1));
        pm1 = fmaxf(pm1, __shfl_xor_sync(0xffffffffu, pm1, 2));
        // exp with LOCAL max (starts immediately; no cross-warp wait)
        float ps0 = 0.f, ps1 = 0.f;
#pragma unroll
        for (int i = 0; i < 8; i++) {
            sv0[i] = exp2f(sv0[i] - pm0); ps0 += sv0[i];
            sv1[i] = exp2f(sv1[i] - pm1); ps1 += sv1[i];
        }
        ps0 += __shfl_xor_sync(0xffffffffu, ps0, 1);
        ps0 += __shfl_xor_sync(0xffffffffu, ps0, 2);
        ps1 += __shfl_xor_sync(0xffffffffu, ps1, 1);
        ps1 += __shfl_xor_sync(0xffffffffu, ps1, 2);
        if (ctid == 0) {
            pmax[nh * 64 + wm + gr]     = pm0;
            pmax[nh * 64 + wm + gr + 8] = pm1;
            psum[nh * 64 + wm + gr]     = ps0;
            psum[nh * 64 + wm + gr + 8] = ps1;
        }
        __syncthreads();   // SINGLE exchange barrier per tile

        // combine halves + history
        float pmA0 = pmax[wm + gr],     pmB0 = pmax[64 + wm + gr];
        float pmA1 = pmax[wm + gr + 8], pmB1 = pmax[64 + wm + gr + 8];
        float mn0 = fmaxf(m0, fmaxf(pmA0, pmB0));
        float mn1 = fmaxf(m1, fmaxf(pmA1, pmB1));
        float al0 = exp2f(m0 - mn0);
        float al1 = exp2f(m1 - mn1);
        l0 = l0 * al0 + psum[wm + gr]     * exp2f(pmA0 - mn0) + psum[64 + wm + gr]     * exp2f(pmB0 - mn0);
        l1 = l1 * al1 + psum[wm + gr + 8] * exp2f(pmA1 - mn1) + psum[64 + wm + gr + 8] * exp2f(pmB1 - mn1);
        m0 = mn0; m1 = mn1;
        // fold local->global correction into this half's P values
        float fs0 = exp2f(pm0 - mn0);
        float fs1 = exp2f(pm1 - mn1);
#pragma unroll
        for (int i = 0; i < 8; i++) { sv0[i] *= fs0; sv1[i] *= fs1; }

#pragma unroll
        for (int nt = 0; nt < 8; nt++) {
            oacc[nt][0] *= al0; oacc[nt][1] *= al0;
            oacc[nt][2] *= al1; oacc[nt][3] *= al1;
        }

#pragma unroll
        for (int kb2 = 0; kb2 < 2; kb2++) {
            uint32_t aph[4], apl[4];
            split_pack(sv0[(2*kb2)*2+0],   sv0[(2*kb2)*2+1],   aph[0], apl[0]);
            split_pack(sv1[(2*kb2)*2+0],   sv1[(2*kb2)*2+1],   aph[1], apl[1]);
            split_pack(sv0[(2*kb2+1)*2+0], sv0[(2*kb2+1)*2+1], aph[2], apl[2]);
            split_pack(sv1[(2*kb2+1)*2+0], sv1[(2*kb2+1)*2+1], aph[3], apl[3]);
            const uint32_t vkb = (uint32_t)(nh * 32 + kb2 * 16) * (FP * 2);
#pragma unroll
            for (int t = 0; t < 4; t++) {
                uint32_t bv[4], bl2[4];
                LDSM4T(bv[0],  bv[1],  bv[2],  bv[3],  vHi + vkb + t * 32);
                LDSM4T(bl2[0], bl2[1], bl2[2], bl2[3], vLo + vkb + t * 32);
                uint32_t bA[2] = {bv[0], bv[1]};
                uint32_t bB[2] = {bv[2], bv[3]};
                uint32_t cA[2] = {bl2[0], bl2[1]};
                uint32_t cB[2] = {bl2[2], bl2[3]};
                mma_bf16(oacc[2*t],   aph, bA);
                mma_bf16(oacc[2*t],   apl, bA);
                mma_bf16(oacc[2*t],   aph, cA);
                mma_bf16(oacc[2*t+1], aph, bB);
                mma_bf16(oacc[2*t+1], apl, bB);
                mma_bf16(oacc[2*t+1], aph, cB);
            }
        }
    }

    __syncthreads();
    float* ox = (float*)(fsm + FL_ST);
    const int pair = warp >> 1;
    if (nh == 0) {
#pragma unroll
        for (int nt = 0; nt < 8; nt++) {
            ox[pair * 1024 + gr * 64 + nt * 8 + c2]           = oacc[nt][0];
            ox[pair * 1024 + gr * 64 + nt * 8 + c2 + 1]       = oacc[nt][1];
            ox[pair * 1024 + (gr + 8) * 64 + nt * 8 + c2]     = oacc[nt][2];
            ox[pair * 1024 + (gr + 8) * 64 + nt * 8 + c2 + 1] = oacc[nt][3];
        }
    }
    __syncthreads();
    if (nh == 1) {
        float inv0 = 1.0f / l0, inv1 = 1.0f / l1;
        size_t r0 = ((size_t)b * Tdim + qt * 64 + wm + gr) * Cdim + h * HDdim;
        size_t r1 = r0 + (size_t)8 * Cdim;
#pragma unroll
        for (int nt = 0; nt < 8; nt++) {
            int d = nt * 8 + c2;
            float v00 = (oacc[nt][0] + ox[pair * 1024 + gr * 64 + d])           * inv0;
            float v01 = (oacc[nt][1] + ox[pair * 1024 + gr * 64 + d + 1])       * inv0;
            float v10 = (oacc[nt][2] + ox[pair * 1024 + (gr + 8) * 64 + d])     * inv1;
            float v11 = (oacc[nt][3] + ox[pair * 1024 + (gr + 8) * 64 + d + 1]) * inv1;
            uint32_t ph, pl;
            split_pack(v00, v01, ph, pl);
            *(uint32_t*)(ohi + r0 + d) = ph;
            *(uint32_t*)(olo + r0 + d) = pl;
            split_pack(v10, v11, ph, pl);
            *(uint32_t*)(ohi + r1 + d) = ph;
            *(uint32_t*)(olo + r1 + d) = pl;
        }
    }
}

// ---------------- host ----------------
static float* symaddr(const void* s) {
    void* p = nullptr;
    cudaGetSymbolAddress(&p, s);
    return (float*)p;
}
static __nv_bfloat16* symaddr_bf(const void* s) {
    void* p = nullptr;
    cudaGetSymbolAddress(&p, s);
    return (__nv_bfloat16*)p;
}

extern "C" void kernel_launch(void* const* d_in, const int* in_sizes, int n_in,
                              void* d_out, int out_size)
{
    const float* x     = (const float*)d_in[0];
    const float* A_log = (const float*)d_in[1];
    const float* Wd    = (const float*)d_in[2];
    const float* bd    = (const float*)d_in[3];
    const float* WB    = (const float*)d_in[4];
    const float* WC    = (const float*)d_in[5];
    const float* Wq    = (const float*)d_in[6];
    const float* bq    = (const float*)d_in[7];
    const float* Wk    = (const float*)d_in[8];
    const float* bk    = (const float*)d_in[9];
    const float* Wv    = (const float*)d_in[10];
    const float* bv    = (const float*)d_in[11];
    const float* Wx    = (const float*)d_in[12];
    const float* bx    = (const float*)d_in[13];
    const float* Wo    = (const float*)d_in[14];
    const float* bo    = (const float*)d_in[15];
    const float* lng   = (const float*)d_in[16];
    const float* lnb   = (const float*)d_in[17];
    const float* temp  = (const float*)d_in[18];
    float* out = (float*)d_out;

    float* xbase = symaddr(g_xbase);
    float* delta = symaddr(g_delta);
    float* Bm    = symaddr(g_Bmat);
    float* Cm    = symaddr(g_Cmat);
    float* y     = symaddr(g_y);
    float* cumD  = symaddr(g_cumD);
    float* hend  = symaddr(g_hend);
    float* hin   = symaddr(g_hin);
    __nv_bfloat16* ahi = symaddr_bf(g_ahi);
    __nv_bfloat16* alo = symaddr_bf(g_alo);
    __nv_bfloat16* whi = symaddr_bf(g_whi);
    __nv_bfloat16* wlo = symaddr_bf(g_wlo);
    __nv_bfloat16* qhi = symaddr_bf(g_qhi);
    __nv_bfloat16* qlo = symaddr_bf(g_qlo);
    __nv_bfloat16* khi = symaddr_bf(g_khi);
    __nv_bfloat16* klo = symaddr_bf(g_klo);
    __nv_bfloat16* vhi = symaddr_bf(g_vhi);
    __nv_bfloat16* vlo = symaddr_bf(g_vlo);

    cudaFuncSetAttribute(bgemm_kernel<0>, cudaFuncAttributeMaxDynamicSharedMemorySize, BG_SMEM);
    cudaFuncSetAttribute(bgemm_kernel<1>, cudaFuncAttributeMaxDynamicSharedMemorySize, BG_SMEM);
    cudaFuncSetAttribute(bgemm_kernel<2>, cudaFuncAttributeMaxDynamicSharedMemorySize, BG_SMEM);
    cudaFuncSetAttribute(flash_kernel, cudaFuncAttributeMaxDynamicSharedMemorySize, FL_SMEM);

    wconv_all_kernel<<<dim3(Cdim / 32, Cdim / 32, 6), 256>>>(Wx, Wd, Wq, Wk, Wv, Wo, whi, wlo);

    dim3 tg(Cdim / 128, Mrows / 128);
    const int ACG = (Mrows * Cdim) / 1024;

    actconv_kernel<<<ACG, 256>>>(x, ahi, alo);
    bgemm_kernel<0><<<tg, 256, BG_SMEM>>>(ahi, alo, whi + 0 * WSZ, wlo + 0 * WSZ, bx, xbase, nullptr, nullptr);
    bgemm_kernel<1><<<tg, 256, BG_SMEM>>>(ahi, alo, whi + 1 * WSZ, wlo + 1 * WSZ, bd, delta, nullptr, nullptr);
    skinny_kernel<<<Mrows / 16, 256>>>(x, WB, WC, Bm, Cm);

    scanA_kernel<<<dim3(Cdim / 16, NCH, Bdim), 256>>>(A_log, delta, xbase, Bm, Cm, y, cumD, hend);
    scanB_kernel<<<(Bdim * Cdim * Sdim) / 256, 256>>>(A_log, cumD, hend, hin);
    scanC_kernel<<<dim3(Cdim / 16, Tdim / 16, Bdim), 256>>>(A_log, Cm, hin, cumD, y);

    addln_kernel<<<Mrows, 256>>>(xbase, y, lng, lnb, ahi, alo);

    bgemm_kernel<2><<<tg, 256, BG_SMEM>>>(ahi, alo, whi + 2 * WSZ, wlo + 2 * WSZ, bq, nullptr, qhi, qlo);
    bgemm_kernel<2><<<tg, 256, BG_SMEM>>>(ahi, alo, whi + 3 * WSZ, wlo + 3 * WSZ, bk, nullptr, khi, klo);
    bgemm_kernel<2><<<tg, 256, BG_SMEM>>>(ahi, alo, whi + 4 * WSZ, wlo + 4 * WSZ, bv, nullptr, vhi, vlo);

    flash_kernel<<<dim3(Tdim / 64, Hdim, Bdim), 256, FL_SMEM>>>(qhi, qlo, khi, klo, vhi, vlo, temp, ahi, alo);

    bgemm_kernel<0><<<tg, 256, BG_SMEM>>>(ahi, alo, whi + 5 * WSZ, wlo + 5 * WSZ, bo, out, nullptr, nullptr);
}

// round 16
// speedup vs baseline: 1.0036x; 1.0036x over previous
#include <cuda_runtime.h>
#include <cuda_bf16.h>
#include <math.h>
#include <stdint.h>

#define Bdim 2
#define Tdim 2048
#define Cdim 1024
#define Hdim 16
#define Sdim 16
#define HDdim 64
#define Mrows (Bdim*Tdim)   /* 4096 */
#define NCH 32              /* scan chunks */
#define CHT (Tdim/NCH)      /* 64 t per chunk */
#define WSZ (Cdim*Cdim)

// ---------------- device scratch (static, no allocation) ----------------
__device__ float g_xbase[Mrows*Cdim];
__device__ float g_delta[Mrows*Cdim];
__device__ float g_Bmat [Mrows*Sdim];
__device__ float g_Cmat [Mrows*Sdim];
__device__ float g_y    [Mrows*Cdim];
__device__ float g_cumD [Mrows*Cdim];
__device__ float g_hend [Bdim*NCH*Cdim*Sdim];
__device__ float g_hin  [Bdim*NCH*Cdim*Sdim];
__device__ __nv_bfloat16 g_ahi[Mrows*Cdim];
__device__ __nv_bfloat16 g_alo[Mrows*Cdim];
__device__ __nv_bfloat16 g_whi[6*WSZ];
__device__ __nv_bfloat16 g_wlo[6*WSZ];
__device__ __nv_bfloat16 g_qhi[Mrows*Cdim];
__device__ __nv_bfloat16 g_qlo[Mrows*Cdim];
__device__ __nv_bfloat16 g_khi[Mrows*Cdim];
__device__ __nv_bfloat16 g_klo[Mrows*Cdim];
__device__ __nv_bfloat16 g_vhi[Mrows*Cdim];
__device__ __nv_bfloat16 g_vlo[Mrows*Cdim];

// ---------------- mma / ldmatrix / cp.async helpers ----------------
__device__ __forceinline__ void mma_bf16(float* d, const uint32_t* a, const uint32_t* b) {
    asm volatile(
        "mma.sync.aligned.m16n8k16.row.col.f32.bf16.bf16.f32 "
        "{%0,%1,%2,%3}, {%4,%5,%6,%7}, {%8,%9}, {%0,%1,%2,%3};"
        : "+f"(d[0]), "+f"(d[1]), "+f"(d[2]), "+f"(d[3])
        : "r"(a[0]), "r"(a[1]), "r"(a[2]), "r"(a[3]), "r"(b[0]), "r"(b[1]));
}
#define LDSM4(r0, r1, r2, r3, addr) \
    asm volatile("ldmatrix.sync.aligned.m8n8.x4.shared.b16 {%0,%1,%2,%3}, [%4];" \
        : "=r"(r0), "=r"(r1), "=r"(r2), "=r"(r3) : "r"(addr))
#define LDSM4T(r0, r1, r2, r3, addr) \
    asm volatile("ldmatrix.sync.aligned.m8n8.x4.trans.shared.b16 {%0,%1,%2,%3}, [%4];" \
        : "=r"(r0), "=r"(r1), "=r"(r2), "=r"(r3) : "r"(addr))
#define CP_ASYNC16(dst, src) \
    asm volatile("cp.async.cg.shared.global [%0], [%1], 16;" :: "r"(dst), "l"(src))
#define CP_COMMIT() asm volatile("cp.async.commit_group;" ::: "memory")
#define CP_WAIT0()  asm volatile("cp.async.wait_group 0;" ::: "memory")

__device__ __forceinline__ uint32_t smem_u32(const void* p) {
    uint32_t a;
    asm("{ .reg .u64 t; cvta.to.shared.u64 t, %1; cvt.u32.u64 %0, t; }"
        : "=r"(a) : "l"(p));
    return a;
}
__device__ __forceinline__ void split_pack(float x, float y, uint32_t& hi, uint32_t& lo) {
    __nv_bfloat16 hx = __float2bfloat16_rn(x), hy = __float2bfloat16_rn(y);
    hi = (uint32_t)__bfloat16_as_ushort(hx) | ((uint32_t)__bfloat16_as_ushort(hy) << 16);
    __nv_bfloat16 lx = __float2bfloat16_rn(x - __bfloat162float(hx));
    __nv_bfloat16 ly = __float2bfloat16_rn(y - __bfloat162float(hy));
    lo = (uint32_t)__bfloat16_as_ushort(lx) | ((uint32_t)__bfloat16_as_ushort(ly) << 16);
}

// ---------------- conversion kernels ----------------
__global__ __launch_bounds__(256)
void actconv_kernel(const float* __restrict__ src,
                    __nv_bfloat16* __restrict__ hi, __nv_bfloat16* __restrict__ lo)
{
    size_t i = ((size_t)blockIdx.x * 256 + threadIdx.x) * 4;
    float4 v = *(const float4*)(src + i);
    __nv_bfloat16 h0 = __float2bfloat16_rn(v.x);
    __nv_bfloat16 h1 = __float2bfloat16_rn(v.y);
    __nv_bfloat16 h2 = __float2bfloat16_rn(v.z);
    __nv_bfloat16 h3 = __float2bfloat16_rn(v.w);
    __nv_bfloat16 l0 = __float2bfloat16_rn(v.x - __bfloat162float(h0));
    __nv_bfloat16 l1 = __float2bfloat16_rn(v.y - __bfloat162float(h1));
    __nv_bfloat16 l2 = __float2bfloat16_rn(v.z - __bfloat162float(h2));
    __nv_bfloat16 l3 = __float2bfloat16_rn(v.w - __bfloat162float(h3));
    ushort4 uh, ul;
    uh.x = __bfloat16_as_ushort(h0); uh.y = __bfloat16_as_ushort(h1);
    uh.z = __bfloat16_as_ushort(h2); uh.w = __bfloat16_as_ushort(h3);
    ul.x = __bfloat16_as_ushort(l0); ul.y = __bfloat16_as_ushort(l1);
    ul.z = __bfloat16_as_ushort(l2); ul.w = __bfloat16_as_ushort(l3);
    *(ushort4*)(hi + i) = uh;
    *(ushort4*)(lo + i) = ul;
}

// All 6 weights in ONE launch
__global__ __launch_bounds__(256)
void wconv_all_kernel(const float* __restrict__ W0, const float* __restrict__ W1,
                      const float* __restrict__ W2, const float* __restrict__ W3,
                      const float* __restrict__ W4, const float* __restrict__ W5,
                      __nv_bfloat16* __restrict__ whi, __nv_bfloat16* __restrict__ wlo)
{
    __shared__ float ts[32][33];
    const int wsel = blockIdx.z;
    const float* W;
    switch (wsel) {
        case 0: W = W0; break;
        case 1: W = W1; break;
        case 2: W = W2; break;
        case 3: W = W3; break;
        case 4: W = W4; break;
        default: W = W5; break;
    }
    __nv_bfloat16* oh = whi + (size_t)wsel * WSZ;
    __nv_bfloat16* ol = wlo + (size_t)wsel * WSZ;

    const int tid = threadIdx.x;
    const int tx = tid & 31, ty = tid >> 5;
    const int n0 = blockIdx.x * 32, k0 = blockIdx.y * 32;
#pragma unroll
    for (int i = 0; i < 4; i++)
        ts[ty + 8 * i][tx] = W[(size_t)(k0 + ty + 8 * i) * Cdim + n0 + tx];
    __syncthreads();
#pragma unroll
    for (int i = 0; i < 4; i++) {
        int r = ty + 8 * i;
        float x = ts[tx][r];
        __nv_bfloat16 h = __float2bfloat16_rn(x);
        __nv_bfloat16 l = __float2bfloat16_rn(x - __bfloat162float(h));
        size_t o = (size_t)(n0 + r) * Cdim + k0 + tx;
        oh[o] = h;
        ol[o] = l;
    }
}

// ---------------- bf16 split tensor GEMM (ldmatrix + cp.async pipeline) --
#define SPITCH 40
#define STG_ELEM (4 * 128 * SPITCH)
#define STG_BYTES (STG_ELEM * 2)
#define ARR_BYTES (128 * SPITCH * 2)
#define BG_SMEM (2 * STG_BYTES)
template<int MODE>
__global__ __launch_bounds__(256, 2)
void bgemm_kernel(const __nv_bfloat16* __restrict__ Ahi, const __nv_bfloat16* __restrict__ Alo,
                  const __nv_bfloat16* __restrict__ Whi, const __nv_bfloat16* __restrict__ Wlo,
                  const float* __restrict__ bias, float* __restrict__ out,
                  __nv_bfloat16* __restrict__ outH, __nv_bfloat16* __restrict__ outL)
{
    extern __shared__ __nv_bfloat16 smb[];

    const int tid  = threadIdx.x;
    const int lane = tid & 31;
    const int warp = tid >> 5;
    const int wm   = (warp >> 2) * 64;
    const int wn   = (warp & 3) * 32;
    const int gr   = lane >> 2;
    const int ctid = lane & 3;
    const int c2   = ctid * 2;
    const int row0 = blockIdx.y * 128;
    const int col0 = blockIdx.x * 128;

    float acc[4][4][4];
#pragma unroll
    for (int i = 0; i < 4; i++)
#pragma unroll
        for (int j = 0; j < 4; j++)
#pragma unroll
            for (int e = 0; e < 4; e++) acc[i][j][e] = 0.f;

    const uint32_t smB = smem_u32(smb);
    uint32_t aad[4], bad[2];
    {
        int arl = lane & 15;
        int ako = (lane >> 4) << 3;
#pragma unroll
        for (int mt = 0; mt < 4; mt++)
            aad[mt] = smB + ((wm + mt * 16 + arl) * SPITCH + ako) * 2;
        int bro = ((lane >> 4) << 3) + (lane & 7);
        int bko = ((lane >> 3) & 1) << 3;
#pragma unroll
        for (int P = 0; P < 2; P++)
            bad[P] = smB + 2 * ARR_BYTES + ((wn + P * 16 + bro) * SPITCH + bko) * 2;
    }

    const int lrow = tid >> 1;
    const int lseg = (tid & 1) * 16;
    const uint32_t sby = (uint32_t)(lrow * SPITCH + lseg) * 2;
    const size_t gAb = (size_t)(row0 + lrow) * Cdim + lseg;
    const size_t gBb = (size_t)(col0 + lrow) * Cdim + lseg;

    {
        uint32_t d0 = smB + sby;
        CP_ASYNC16(d0,                 Ahi + gAb);
        CP_ASYNC16(d0 + 16,            Ahi + gAb + 8);
        CP_ASYNC16(d0 + ARR_BYTES,     Alo + gAb);
        CP_ASYNC16(d0 + ARR_BYTES+16,  Alo + gAb + 8);
        CP_ASYNC16(d0 + 2*ARR_BYTES,   Whi + gBb);
        CP_ASYNC16(d0 + 2*ARR_BYTES+16,Whi + gBb + 8);
        CP_ASYNC16(d0 + 3*ARR_BYTES,   Wlo + gBb);
        CP_ASYNC16(d0 + 3*ARR_BYTES+16,Wlo + gBb + 8);
        CP_COMMIT();
    }

    for (int ch = 0; ch < 32; ch++) {
        CP_WAIT0();
        __syncthreads();

        if (ch + 1 < 32) {
            int k0 = (ch + 1) * 32;
            uint32_t d0 = smB + ((ch + 1) & 1) * STG_BYTES + sby;
            CP_ASYNC16(d0,                 Ahi + gAb + k0);
            CP_ASYNC16(d0 + 16,            Ahi + gAb + k0 + 8);
            CP_ASYNC16(d0 + ARR_BYTES,     Alo + gAb + k0);
            CP_ASYNC16(d0 + ARR_BYTES+16,  Alo + gAb + k0 + 8);
            CP_ASYNC16(d0 + 2*ARR_BYTES,   Whi + gBb + k0);
            CP_ASYNC16(d0 + 2*ARR_BYTES+16,Whi + gBb + k0 + 8);
            CP_ASYNC16(d0 + 3*ARR_BYTES,   Wlo + gBb + k0);
            CP_ASYNC16(d0 + 3*ARR_BYTES+16,Wlo + gBb + k0 + 8);
            CP_COMMIT();
        }

        const uint32_t sb = (ch & 1) * STG_BYTES;
#pragma unroll
        for (int ks = 0; ks < 2; ks++) {
            const uint32_t ksb = sb + ks * 32;
            uint32_t ahf[4][4], alf[4][4];
#pragma unroll
            for (int mt = 0; mt < 4; mt++) {
                LDSM4(ahf[mt][0], ahf[mt][1], ahf[mt][2], ahf[mt][3], aad[mt] + ksb);
                LDSM4(alf[mt][0], alf[mt][1], alf[mt][2], alf[mt][3], aad[mt] + ksb + ARR_BYTES);
            }
            uint32_t bhf[4][2], blf[4][2];
#pragma unroll
            for (int P = 0; P < 2; P++) {
                LDSM4(bhf[2*P][0], bhf[2*P][1], bhf[2*P+1][0], bhf[2*P+1][1], bad[P] + ksb);
                LDSM4(blf[2*P][0], blf[2*P][1], blf[2*P+1][0], blf[2*P+1][1], bad[P] + ksb + ARR_BYTES);
            }
#pragma unroll
            for (int mt = 0; mt < 4; mt++)
#pragma unroll
                for (int nt = 0; nt < 4; nt++) {
                    mma_bf16(acc[mt][nt], ahf[mt], bhf[nt]);
                    mma_bf16(acc[mt][nt], alf[mt], bhf[nt]);
                    mma_bf16(acc[mt][nt], ahf[mt], blf[nt]);
                }
        }
    }

#pragma unroll
    for (int mt = 0; mt < 4; mt++) {
#pragma unroll
        for (int nt = 0; nt < 4; nt++) {
            int c = col0 + wn + nt * 8 + c2;
            float2 bb = *(const float2*)(bias + c);
#pragma unroll
            for (int half = 0; half < 2; half++) {
                int r = row0 + wm + mt * 16 + gr + half * 8;
                float vx = acc[mt][nt][half * 2 + 0] + bb.x;
                float vy = acc[mt][nt][half * 2 + 1] + bb.y;
                if (MODE == 1) {
                    vx = (vx > 20.f) ? vx : log1pf(expf(vx));
                    vy = (vy > 20.f) ? vy : log1pf(expf(vy));
                }
                if (MODE == 2) {
                    int b = r >> 11, t = r & (Tdim - 1);
                    int hh = c >> 6, d = c & 63;
                    size_t di = (((size_t)(b * Hdim + hh) * Tdim + t) << 6) + d;
                    uint32_t ph, pl;
                    split_pack(vx, vy, ph, pl);
                    *(uint32_t*)(outH + di) = ph;
                    *(uint32_t*)(outL + di) = pl;
                } else {
                    *(float2*)(out + (size_t)r * Cdim + c) = make_float2(vx, vy);
                }
            }
        }
    }
}

// ---------------- skinny GEMM ----------------
__global__ __launch_bounds__(256)
void skinny_kernel(const float* __restrict__ x, const float* __restrict__ WB,
                   const float* __restrict__ WC,
                   float* __restrict__ Bm, float* __restrict__ Cm)
{
    __shared__ float wb[128 * 16];
    __shared__ float wc[128 * 16];
    __shared__ float xs[16][128];
    const int tid = threadIdx.x;
    const int m0  = blockIdx.x * 16;
    const int rl  = tid >> 4;
    const int s   = tid & 15;
    float accB = 0.f, accC = 0.f;

    for (int k0 = 0; k0 < Cdim; k0 += 128) {
#pragma unroll
        for (int u = 0; u < 2; u++) {
            int idx = tid * 8 + u * 4;
            *(float4*)&wb[idx] = *(const float4*)(WB + k0 * 16 + idx);
            *(float4*)&wc[idx] = *(const float4*)(WC + k0 * 16 + idx);
        }
        {
            int row = tid >> 4;
            int cc  = (tid & 15) * 8;
            const float* xp = x + (size_t)(m0 + row) * Cdim + k0 + cc;
            *(float4*)&xs[row][cc]     = *(const float4*)(xp);
            *(float4*)&xs[row][cc + 4] = *(const float4*)(xp + 4);
        }
        __syncthreads();
#pragma unroll 8
        for (int kk = 0; kk < 128; kk++) {
            float xv = xs[rl][kk];
            accB = fmaf(xv, wb[kk * 16 + s], accB);
            accC = fmaf(xv, wc[kk * 16 + s], accC);
        }
        __syncthreads();
    }
    Bm[(size_t)(m0 + rl) * 16 + s] = accB;
    Cm[(size_t)(m0 + rl) * 16 + s] = accC;
}

// ================= chunked SSM scan =================
#define TTA 32
__global__ __launch_bounds__(256)
void scanA_kernel(const float* __restrict__ A_log,
                  const float* __restrict__ delta,
                  const float* __restrict__ xb,
                  const float* __restrict__ Bm,
                  const float* __restrict__ Cm,
                  float* __restrict__ ylocal,
                  float* __restrict__ cumD,
                  float* __restrict__ hend)
{
    __shared__ float2 sdx[TTA][16];
    __shared__ float2 sbc[TTA][16];

    const int tid = threadIdx.x;
    const int s   = tid & 15;
    const int cl  = tid >> 4;
    const int c0  = blockIdx.x * 16;
    const int ch  = blockIdx.y;
    const int b   = blockIdx.z;
    const int c   = c0 + cl;
    const int t00 = ch * CHT;
    const float LOG2E = 1.4426950408889634f;
    const float a2 = -expf(A_log[c * Sdim + s]) * LOG2E;

    float h = 0.f, cum = 0.f;

    for (int t0 = t00; t0 < t00 + CHT; t0 += TTA) {
        __syncthreads();
#pragma unroll
        for (int u = 0; u < 2; u++) {
            int e = tid + u * 256;
            int tt = e >> 4, cc = e & 15;
            size_t g = ((size_t)b * Tdim + t0 + tt) * Cdim + c0 + cc;
            sdx[tt][cc] = make_float2(delta[g], xb[g]);
        }
#pragma unroll
        for (int u = 0; u < 2; u++) {
            int e = tid + u * 256;
            int tt = e >> 4, ss = e & 15;
            size_t g = ((size_t)b * Tdim + t0 + tt) * Sdim + ss;
            sbc[tt][ss] = make_float2(Bm[g], Cm[g]);
        }
        __syncthreads();

#pragma unroll
        for (int tt = 0; tt < TTA; tt++) {
            float2 dx = sdx[tt][cl];
            float2 bc = sbc[tt][s];
            cum += dx.x;
            float e = exp2f(dx.x * a2);
            h = fmaf(e, h, dx.x * dx.y * bc.x);
            float p = h * bc.y;
            p += __shfl_xor_sync(0xffffffffu, p, 8);
            p += __shfl_xor_sync(0xffffffffu, p, 4);
            p += __shfl_xor_sync(0xffffffffu, p, 2);
            p += __shfl_xor_sync(0xffffffffu, p, 1);
            if (s == 0) {
                size_t g = ((size_t)b * Tdim + t0 + tt) * Cdim + c;
                ylocal[g] = p;
                cumD[g]   = cum;
            }
        }
    }
    hend[(((size_t)b * NCH + ch) * Cdim + c) * Sdim + s] = h;
}

__global__ __launch_bounds__(256)
void scanB_kernel(const float* __restrict__ A_log,
                  const float* __restrict__ cumD,
                  const float* __restrict__ hend,
                  float* __restrict__ hin)
{
    const int gid = blockIdx.x * 256 + threadIdx.x;
    const int s = gid & 15;
    const int c = (gid >> 4) & (Cdim - 1);
    const int b = gid >> 14;
    const float LOG2E = 1.4426950408889634f;
    const float a2 = -expf(A_log[c * Sdim + s]) * LOG2E;

    float h = 0.f;
#pragma unroll
    for (int k = 0; k < NCH; k++) {
        size_t idx = (((size_t)b * NCH + k) * Cdim + c) * Sdim + s;
        hin[idx] = h;
        float sd = cumD[((size_t)b * Tdim + k * CHT + CHT - 1) * Cdim + c];
        h = fmaf(exp2f(a2 * sd), h, hend[idx]);
    }
}

__global__ __launch_bounds__(256)
void scanC_kernel(const float* __restrict__ A_log,
                  const float* __restrict__ Cm,
                  const float* __restrict__ hin,
                  const float* __restrict__ cumD,
                  float* __restrict__ y)
{
    __shared__ float a2s[16][17];
    __shared__ float hns[16][17];
    __shared__ float cts[16][16];

    const int tid = threadIdx.x;
    const int c0  = blockIdx.x * 16;
    const int t0  = blockIdx.y * 16;
    const int b   = blockIdx.z;
    const int ch  = t0 / CHT;
    const float LOG2E = 1.4426950408889634f;

    {
        int i = tid >> 4, j = tid & 15;
        a2s[i][j] = -expf(A_log[(c0 + i) * Sdim + j]) * LOG2E;
        hns[i][j] = hin[(((size_t)b * NCH + ch) * Cdim + c0 + i) * Sdim + j];
        cts[i][j] = Cm[((size_t)b * Tdim + t0 + i) * Sdim + j];
    }
    __syncthreads();

    const int tl = tid >> 4;
    const int cl = tid & 15;
    size_t g = ((size_t)b * Tdim + t0 + tl) * Cdim + c0 + cl;
    float cd  = cumD[g];
    float acc = y[g];
#pragma unroll
    for (int s = 0; s < 16; s++)
        acc = fmaf(cts[tl][s] * hns[cl][s], exp2f(a2s[cl][s] * cd), acc);
    y[g] = acc;
}

// ---------------- add + LayerNorm, emits bf16 hi/lo directly -------------
__global__ __launch_bounds__(256)
void addln_kernel(const float* __restrict__ xb, const float* __restrict__ y,
                  const float* __restrict__ gam, const float* __restrict__ bet,
                  __nv_bfloat16* __restrict__ ohi, __nv_bfloat16* __restrict__ olo)
{
    __shared__ float red[16];
    const int row = blockIdx.x, tid = threadIdx.x;
    const float* p1 = xb + (size_t)row * Cdim;
    const float* p2 = y  + (size_t)row * Cdim;
    float v[4]; float s = 0.f, s2 = 0.f;
#pragma unroll
    for (int i = 0; i < 4; i++) {
        int idx = tid + i * 256;
        v[i] = p1[idx] + p2[idx];
        s += v[i]; s2 += v[i] * v[i];
    }
#pragma unroll
    for (int o = 16; o; o >>= 1) {
        s  += __shfl_xor_sync(0xffffffffu, s,  o);
        s2 += __shfl_xor_sync(0xffffffffu, s2, o);
    }
    if ((tid & 31) == 0) { red[tid >> 5] = s; red[(tid >> 5) + 8] = s2; }
    __syncthreads();
    float S = 0.f, S2 = 0.f;
#pragma unroll
    for (int w = 0; w < 8; w++) { S += red[w]; S2 += red[w + 8]; }
    float mean = S * (1.f / Cdim);
    float var  = S2 * (1.f / Cdim) - mean * mean;
    float rs   = rsqrtf(var + 1e-5f);
#pragma unroll
    for (int i = 0; i < 4; i++) {
        int idx = tid + i * 256;
        float val = (v[i] - mean) * rs * gam[idx] + bet[idx];
        __nv_bfloat16 h = __float2bfloat16_rn(val);
        __nv_bfloat16 l = __float2bfloat16_rn(val - __bfloat162float(h));
        ohi[(size_t)row * Cdim + idx] = h;
        olo[(size_t)row * Cdim + idx] = l;
    }
}

// ---------------- flash attention on tensor cores (bf16 3-pass) ----------
// Longest-first CTA order: qt = gridDim.x-1-blockIdx.x so heavy (large-qt)
// CTAs launch in wave 0 and short ones backfill (causal-imbalance tail fix).
#define FP 72
#define FL_ARRE 4608
#define FL_ARRB 9216
#define FL_Q0 0
#define FL_Q1 FL_ARRE
#define FL_ST (2*FL_ARRE)
#define FL_STGB (4*FL_ARRB)
#define FL_F32 (FL_ST + 8*FL_ARRE)
#define FL_SMEM (FL_F32*2 + 1024)
__global__ __launch_bounds__(256, 2)
void flash_kernel(const __nv_bfloat16* __restrict__ qhi, const __nv_bfloat16* __restrict__ qlo,
                  const __nv_bfloat16* __restrict__ khi, const __nv_bfloat16* __restrict__ klo,
                  const __nv_bfloat16* __restrict__ vhi, const __nv_bfloat16* __restrict__ vlo,
                  const float* __restrict__ temp,
                  __nv_bfloat16* __restrict__ ohi, __nv_bfloat16* __restrict__ olo)
{
    extern __shared__ __nv_bfloat16 fsm[];
    const uint32_t smB = smem_u32(fsm);
    float* pmax = (float*)(fsm + FL_F32);
    float* psum = pmax + 128;

    const int tid = threadIdx.x;
    const int lane = tid & 31;
    const int warp = tid >> 5;
    const int wm   = (warp >> 1) * 16;
    const int nh   = warp & 1;
    const int gr   = lane >> 2;
    const int ctid = lane & 3;
    const int c2   = ctid * 2;

    const int qt = (int)gridDim.x - 1 - (int)blockIdx.x;   // longest-first
    const int h = blockIdx.y, b = blockIdx.z;
    const int bh = b * Hdim + h;
    const __nv_bfloat16* qhb = qhi + (((size_t)bh * Tdim) + qt * 64) * 64;
    const __nv_bfloat16* qlb = qlo + (((size_t)bh * Tdim) + qt * 64) * 64;
    const __nv_bfloat16* khb = khi + ((size_t)bh * Tdim) * 64;
    const __nv_bfloat16* klb = klo + ((size_t)bh * Tdim) * 64;
    const __nv_bfloat16* vhb = vhi + ((size_t)bh * Tdim) * 64;
    const __nv_bfloat16* vlb = vlo + ((size_t)bh * Tdim) * 64;

    float tv = temp[h];
    float sp = (tv > 20.f) ? tv : log1pf(expf(tv));
    const float sc = sp * (1.4426950408889634f / 8.0f);

    {
        int row = tid >> 2, col = (tid & 3) * 16;
        *(uint4*)&fsm[FL_Q0 + row * FP + col]     = *(const uint4*)(qhb + row * 64 + col);
        *(uint4*)&fsm[FL_Q0 + row * FP + col + 8] = *(const uint4*)(qhb + row * 64 + col + 8);
        *(uint4*)&fsm[FL_Q1 + row * FP + col]     = *(const uint4*)(qlb + row * 64 + col);
        *(uint4*)&fsm[FL_Q1 + row * FP + col + 8] = *(const uint4*)(qlb + row * 64 + col + 8);
    }

    const int arl = lane & 15;
    const int ako = (lane >> 4) << 3;
    const uint32_t aQh = smB + (FL_Q0 + (wm + arl) * FP + ako) * 2;
    const uint32_t aQl = smB + (FL_Q1 + (wm + arl) * FP + ako) * 2;
    const int bro = ((lane >> 4) << 3) + (lane & 7);
    const int bko = ((lane >> 3) & 1) << 3;
    const uint32_t bKoff = (uint32_t)((nh * 32 + bro) * FP + bko) * 2;
    const uint32_t vOff = (uint32_t)(((((lane >> 3) & 1) * 8 + (lane & 7)) * FP) + ((lane >> 4) * 8)) * 2;

    const int ca = tid >> 6;
    const int crow = tid & 63;
    const __nv_bfloat16* csrc = (ca == 0) ? khb : (ca == 1) ? klb : (ca == 2) ? vhb : vlb;

    float m0 = -1e30f, m1 = -1e30f, l0 = 0.f, l1 = 0.f;
    float oacc[8][4];
#pragma unroll
    for (int nt = 0; nt < 8; nt++)
#pragma unroll
        for (int e = 0; e < 4; e++) oacc[nt][e] = 0.f;

    {
        uint32_t dst = smB + FL_ST * 2 + ca * FL_ARRB + crow * (FP * 2);
        const __nv_bfloat16* g = csrc + (size_t)crow * 64;
#pragma unroll
        for (int c = 0; c < 8; c++) CP_ASYNC16(dst + c * 16, g + c * 8);
        CP_COMMIT();
    }

    for (int j = 0; j <= qt; j++) {
        CP_WAIT0();
        __syncthreads();

        if (j + 1 <= qt) {
            uint32_t dst = smB + FL_ST * 2 + ((j + 1) & 1) * FL_STGB + ca * FL_ARRB + crow * (FP * 2);
            const __nv_bfloat16* g = csrc + (size_t)((j + 1) * 64 + crow) * 64;
#pragma unroll
            for (int c = 0; c < 8; c++) CP_ASYNC16(dst + c * 16, g + c * 8);
            CP_COMMIT();
        }

        const uint32_t stgB = smB + FL_ST * 2 + (j & 1) * FL_STGB;
        const uint32_t kHi = stgB + bKoff;
        const uint32_t kLo = kHi + FL_ARRB;
        const uint32_t vHi = stgB + 2 * FL_ARRB + vOff;
        const uint32_t vLo = vHi + FL_ARRB;

        float sacc[4][4];
#pragma unroll
        for (int nt = 0; nt < 4; nt++)
#pragma unroll
            for (int e = 0; e < 4; e++) sacc[nt][e] = 0.f;
#pragma unroll
        for (int kb = 0; kb < 4; kb++) {
            uint32_t ah[4], al_[4];
            LDSM4(ah[0], ah[1], ah[2], ah[3], aQh + kb * 32);
            LDSM4(al_[0], al_[1], al_[2], al_[3], aQl + kb * 32);
            uint32_t bh_[4][2], bl_[4][2];
#pragma unroll
            for (int P = 0; P < 2; P++) {
                LDSM4(bh_[2*P][0], bh_[2*P][1], bh_[2*P+1][0], bh_[2*P+1][1], kHi + P * (16 * FP * 2) + kb * 32);
                LDSM4(bl_[2*P][0], bl_[2*P][1], bl_[2*P+1][0], bl_[2*P+1][1], kLo + P * (16 * FP * 2) + kb * 32);
            }
#pragma unroll
            for (int nt = 0; nt < 4; nt++) {
                mma_bf16(sacc[nt], ah,  bh_[nt]);
                mma_bf16(sacc[nt], al_, bh_[nt]);
                mma_bf16(sacc[nt], ah,  bl_[nt]);
            }
        }

        // ---- scale, mask; local softmax stats, single exchange ----
        const bool diag = (j == qt);
        float sv0[8], sv1[8];
#pragma unroll
        for (int nt = 0; nt < 4; nt++)
#pragma unroll
            for (int e = 0; e < 2; e++) {
                int cl = nh * 32 + nt * 8 + c2 + e;
                float x0 = sacc[nt][e]     * sc;
                float x1 = sacc[nt][2 + e] * sc;
                if (diag) {
                    if (cl > wm + gr)     x0 = -1e30f;
                    if (cl > wm + gr + 8) x1 = -1e30f;
                }
                sv0[nt * 2 + e] = x0;
                sv1[nt * 2 + e] = x1;
            }
        float pm0 = sv0[0], pm1 = sv1[0];
#pragma unroll
        for (int i = 1; i < 8; i++) { pm0 = fmaxf(pm0, sv0[i]); pm1 = fmaxf(pm1, sv1[i]); }
        pm0 = fmaxf(pm0, __shfl_xor_sync(0xffffffffu, pm0, 1));
        pm0 = fmaxf(pm0, __shfl_xor_sync(0xffffffffu, pm0, 2));
        pm1 = fmaxf(pm1, __shfl_xor_sync(0xffffffffu, pm1, 1));
        pm1 = fmaxf(pm1, __shfl_xor_sync(0xffffffffu, pm1, 2));
        float ps0 = 0.f, ps1 = 0.f;
#pragma unroll
        for (int i = 0; i < 8; i++) {
            sv0[i] = exp2f(sv0[i] - pm0); ps0 += sv0[i];
            sv1[i] = exp2f(sv1[i] - pm1); ps1 += sv1[i];
        }
        ps0 += __shfl_xor_sync(0xffffffffu, ps0, 1);
        ps0 += __shfl_xor_sync(0xffffffffu, ps0, 2);
        ps1 += __shfl_xor_sync(0xffffffffu, ps1, 1);
        ps1 += __shfl_xor_sync(0xffffffffu, ps1, 2);
        if (ctid == 0) {
            pmax[nh * 64 + wm + gr]     = pm0;
            pmax[nh * 64 + wm + gr + 8] = pm1;
            psum[nh * 64 + wm + gr]     = ps0;
            psum[nh * 64 + wm + gr + 8] = ps1;
        }
        __syncthreads();

        float pmA0 = pmax[wm + gr],     pmB0 = pmax[64 + wm + gr];
        float pmA1 = pmax[wm + gr + 8], pmB1 = pmax[64 + wm + gr + 8];
        float mn0 = fmaxf(m0, fmaxf(pmA0, pmB0));
        float mn1 = fmaxf(m1, fmaxf(pmA1, pmB1));
        float al0 = exp2f(m0 - mn0);
        float al1 = exp2f(m1 - mn1);
        l0 = l0 * al0 + psum[wm + gr]     * exp2f(pmA0 - mn0) + psum[64 + wm + gr]     * exp2f(pmB0 - mn0);
        l1 = l1 * al1 + psum[wm + gr + 8] * exp2f(pmA1 - mn1) + psum[64 + wm + gr + 8] * exp2f(pmB1 - mn1);
        m0 = mn0; m1 = mn1;
        float fs0 = exp2f(pm0 - mn0);
        float fs1 = exp2f(pm1 - mn1);
#pragma unroll
        for (int i = 0; i < 8; i++) { sv0[i] *= fs0; sv1[i] *= fs1; }

#pragma unroll
        for (int nt = 0; nt < 8; nt++) {
            oacc[nt][0] *= al0; oacc[nt][1] *= al0;
            oacc[nt][2] *= al1; oacc[nt][3] *= al1;
        }

#pragma unroll
        for (int kb2 = 0; kb2 < 2; kb2++) {
            uint32_t aph[4], apl[4];
            split_pack(sv0[(2*kb2)*2+0],   sv0[(2*kb2)*2+1],   aph[0], apl[0]);
            split_pack(sv1[(2*kb2)*2+0],   sv1[(2*kb2)*2+1],   aph[1], apl[1]);
            split_pack(sv0[(2*kb2+1)*2+0], sv0[(2*kb2+1)*2+1], aph[2], apl[2]);
            split_pack(sv1[(2*kb2+1)*2+0], sv1[(2*kb2+1)*2+1], aph[3], apl[3]);
            const uint32_t vkb = (uint32_t)(nh * 32 + kb2 * 16) * (FP * 2);
#pragma unroll
            for (int t = 0; t < 4; t++) {
                uint32_t bv[4], bl2[4];
                LDSM4T(bv[0],  bv[1],  bv[2],  bv[3],  vHi + vkb + t * 32);
                LDSM4T(bl2[0], bl2[1], bl2[2], bl2[3], vLo + vkb + t * 32);
                uint32_t bA[2] = {bv[0], bv[1]};
                uint32_t bB[2] = {bv[2], bv[3]};
                uint32_t cA[2] = {bl2[0], bl2[1]};
                uint32_t cB[2] = {bl2[2], bl2[3]};
                mma_bf16(oacc[2*t],   aph, bA);
                mma_bf16(oacc[2*t],   apl, bA);
                mma_bf16(oacc[2*t],   aph, cA);
                mma_bf16(oacc[2*t+1], aph, bB);
                mma_bf16(oacc[2*t+1], apl, bB);
                mma_bf16(oacc[2*t+1], aph, cB);
            }
        }
    }

    __syncthreads();
    float* ox = (float*)(fsm + FL_ST);
    const int pair = warp >> 1;
    if (nh == 0) {
#pragma unroll
        for (int nt = 0; nt < 8; nt++) {
            ox[pair * 1024 + gr * 64 + nt * 8 + c2]           = oacc[nt][0];
            ox[pair * 1024 + gr * 64 + nt * 8 + c2 + 1]       = oacc[nt][1];
            ox[pair * 1024 + (gr + 8) * 64 + nt * 8 + c2]     = oacc[nt][2];
            ox[pair * 1024 + (gr + 8) * 64 + nt * 8 + c2 + 1] = oacc[nt][3];
        }
    }
    __syncthreads();
    if (nh == 1) {
        float inv0 = 1.0f / l0, inv1 = 1.0f / l1;
        size_t r0 = ((size_t)b * Tdim + qt * 64 + wm + gr) * Cdim + h * HDdim;
        size_t r1 = r0 + (size_t)8 * Cdim;
#pragma unroll
        for (int nt = 0; nt < 8; nt++) {
            int d = nt * 8 + c2;
            float v00 = (oacc[nt][0] + ox[pair * 1024 + gr * 64 + d])           * inv0;
            float v01 = (oacc[nt][1] + ox[pair * 1024 + gr * 64 + d + 1])       * inv0;
            float v10 = (oacc[nt][2] + ox[pair * 1024 + (gr + 8) * 64 + d])     * inv1;
            float v11 = (oacc[nt][3] + ox[pair * 1024 + (gr + 8) * 64 + d + 1]) * inv1;
            uint32_t ph, pl;
            split_pack(v00, v01, ph, pl);
            *(uint32_t*)(ohi + r0 + d) = ph;
            *(uint32_t*)(olo + r0 + d) = pl;
            split_pack(v10, v11, ph, pl);
            *(uint32_t*)(ohi + r1 + d) = ph;
            *(uint32_t*)(olo + r1 + d) = pl;
        }
    }
}

// ---------------- host ----------------
static float* symaddr(const void* s) {
    void* p = nullptr;
    cudaGetSymbolAddress(&p, s);
    return (float*)p;
}
static __nv_bfloat16* symaddr_bf(const void* s) {
    void* p = nullptr;
    cudaGetSymbolAddress(&p, s);
    return (__nv_bfloat16*)p;
}

extern "C" void kernel_launch(void* const* d_in, const int* in_sizes, int n_in,
                              void* d_out, int out_size)
{
    const float* x     = (const float*)d_in[0];
    const float* A_log = (const float*)d_in[1];
    const float* Wd    = (const float*)d_in[2];
    const float* bd    = (const float*)d_in[3];
    const float* WB    = (const float*)d_in[4];
    const float* WC    = (const float*)d_in[5];
    const float* Wq    = (const float*)d_in[6];
    const float* bq    = (const float*)d_in[7];
    const float* Wk    = (const float*)d_in[8];
    const float* bk    = (const float*)d_in[9];
    const float* Wv    = (const float*)d_in[10];
    const float* bv    = (const float*)d_in[11];
    const float* Wx    = (const float*)d_in[12];
    const float* bx    = (const float*)d_in[13];
    const float* Wo    = (const float*)d_in[14];
    const float* bo    = (const float*)d_in[15];
    const float* lng   = (const float*)d_in[16];
    const float* lnb   = (const float*)d_in[17];
    const float* temp  = (const float*)d_in[18];
    float* out = (float*)d_out;

    float* xbase = symaddr(g_xbase);
    float* delta = symaddr(g_delta);
    float* Bm    = symaddr(g_Bmat);
    float* Cm    = symaddr(g_Cmat);
    float* y     = symaddr(g_y);
    float* cumD  = symaddr(g_cumD);
    float* hend  = symaddr(g_hend);
    float* hin   = symaddr(g_hin);
    __nv_bfloat16* ahi = symaddr_bf(g_ahi);
    __nv_bfloat16* alo = symaddr_bf(g_alo);
    __nv_bfloat16* whi = symaddr_bf(g_whi);
    __nv_bfloat16* wlo = symaddr_bf(g_wlo);
    __nv_bfloat16* qhi = symaddr_bf(g_qhi);
    __nv_bfloat16* qlo = symaddr_bf(g_qlo);
    __nv_bfloat16* khi = symaddr_bf(g_khi);
    __nv_bfloat16* klo = symaddr_bf(g_klo);
    __nv_bfloat16* vhi = symaddr_bf(g_vhi);
    __nv_bfloat16* vlo = symaddr_bf(g_vlo);

    cudaFuncSetAttribute(bgemm_kernel<0>, cudaFuncAttributeMaxDynamicSharedMemorySize, BG_SMEM);
    cudaFuncSetAttribute(bgemm_kernel<1>, cudaFuncAttributeMaxDynamicSharedMemorySize, BG_SMEM);
    cudaFuncSetAttribute(bgemm_kernel<2>, cudaFuncAttributeMaxDynamicSharedMemorySize, BG_SMEM);
    cudaFuncSetAttribute(flash_kernel, cudaFuncAttributeMaxDynamicSharedMemorySize, FL_SMEM);

    wconv_all_kernel<<<dim3(Cdim / 32, Cdim / 32, 6), 256>>>(Wx, Wd, Wq, Wk, Wv, Wo, whi, wlo);

    dim3 tg(Cdim / 128, Mrows / 128);
    const int ACG = (Mrows * Cdim) / 1024;

    actconv_kernel<<<ACG, 256>>>(x, ahi, alo);
    bgemm_kernel<0><<<tg, 256, BG_SMEM>>>(ahi, alo, whi + 0 * WSZ, wlo + 0 * WSZ, bx, xbase, nullptr, nullptr);
    bgemm_kernel<1><<<tg, 256, BG_SMEM>>>(ahi, alo, whi + 1 * WSZ, wlo + 1 * WSZ, bd, delta, nullptr, nullptr);
    skinny_kernel<<<Mrows / 16, 256>>>(x, WB, WC, Bm, Cm);

    scanA_kernel<<<dim3(Cdim / 16, NCH, Bdim), 256>>>(A_log, delta, xbase, Bm, Cm, y, cumD, hend);
    scanB_kernel<<<(Bdim * Cdim * Sdim) / 256, 256>>>(A_log, cumD, hend, hin);
    scanC_kernel<<<dim3(Cdim / 16, Tdim / 16, Bdim), 256>>>(A_log, Cm, hin, cumD, y);

    addln_kernel<<<Mrows, 256>>>(xbase, y, lng, lnb, ahi, alo);

    bgemm_kernel<2><<<tg, 256, BG_SMEM>>>(ahi, alo, whi + 2 * WSZ, wlo + 2 * WSZ, bq, nullptr, qhi, qlo);
    bgemm_kernel<2><<<tg, 256, BG_SMEM>>>(ahi, alo, whi + 3 * WSZ, wlo + 3 * WSZ, bk, nullptr, khi, klo);
    bgemm_kernel<2><<<tg, 256, BG_SMEM>>>(ahi, alo, whi + 4 * WSZ, wlo + 4 * WSZ, bv, nullptr, vhi, vlo);

    flash_kernel<<<dim3(Tdim / 64, Hdim, Bdim), 256, FL_SMEM>>>(qhi, qlo, khi, klo, vhi, vlo, temp, ahi, alo);

    bgemm_kernel<0><<<tg, 256, BG_SMEM>>>(ahi, alo, whi + 5 * WSZ, wlo + 5 * WSZ, bo, out, nullptr, nullptr);
}